// round 7
// baseline (speedup 1.0000x reference)
#include <cuda_runtime.h>
#include <cstdint>

// Problem constants (fixed shapes per reference)
#define B_DIM 4
#define P_DIM 2
#define T_DIM 1024
#define F_DIM 1024
#define D_DIM 16
#define CHUNK 128
#define NCHUNK (F_DIM / CHUNK)   // 8
#define T_PER_BLOCK 8

// Per-(b,d,chunk) integer shifts. 4*16*8 = 512 ints.
__device__ int g_shift[B_DIM * D_DIM * NCHUNK];

// ---------------------------------------------------------------------------
// Kernel 1: compute delays (written to output tail) and chunk shifts.
// grid = B*D blocks, 128 threads each.
// ---------------------------------------------------------------------------
__global__ void dedisp_prep_kernel(const float* __restrict__ dm,
                                   const float* __restrict__ df,
                                   float* __restrict__ delays_out)
{
    const int bd = blockIdx.x;            // 0..63 : (b*16 + d)
    const float dmv = dm[bd];
    const int t = threadIdx.x;            // 0..127

    __shared__ float sh[F_DIM];

    // Each thread covers f = t, t+128, ..., one element per chunk.
    #pragma unroll
    for (int k = 0; k < NCHUNK; k++) {
        const int f = k * CHUNK + t;
        const float d = dmv * df[f];      // fp32 product, matches reference
        delays_out[(size_t)bd * F_DIM + f] = d;
        sh[f] = d;
    }
    __syncthreads();

    // 8 threads each reduce one chunk of 128 values sequentially.
    if (t < NCHUNK) {
        float sum = 0.0f;
        const float* base = sh + t * CHUNK;
        #pragma unroll 8
        for (int i = 0; i < CHUNK; i++) sum += base[i];
        const float mean = sum * (1.0f / 128.0f);   // exact scale by 2^-7
        int s = (int)truncf(mean);
        if (s < 0) s = 0;
        s &= (T_DIM - 1);                 // safety (s <= ~204 in practice)
        g_shift[bd * NCHUNK + t] = s;
    }
}

// ---------------------------------------------------------------------------
// Kernel 2: the gather-copy.
// grid = B*D*P*(T/T_PER_BLOCK) = 16384 blocks, 256 threads.
// Each thread moves T_PER_BLOCK float4's (one per t-row it owns).
// Warp w handles chunk w -> shift is warp-uniform.
// ---------------------------------------------------------------------------
__global__ __launch_bounds__(256)
void dedisp_gather_kernel(const float4* __restrict__ x,
                          float4* __restrict__ out)
{
    const int bi  = blockIdx.x;
    const int tb  = bi & (T_DIM / T_PER_BLOCK - 1);   // 0..127
    const int p   = (bi >> 7) & (P_DIM - 1);
    const int d   = (bi >> 8) & (D_DIM - 1);
    const int b   = bi >> 12;

    const int tid = threadIdx.x;          // 0..255, f4 index
    const int c   = tid >> 5;             // chunk = warp id

    const int s = g_shift[(b * D_DIM + d) * NCHUNK + c];

    const int F4 = F_DIM / 4;             // 256 float4 per row

    const float4* __restrict__ xrow =
        x + (size_t)(b * P_DIM + p) * T_DIM * F4;

    float4* __restrict__ orow =
        out + ((size_t)((b * D_DIM + d) * P_DIM + p) * T_DIM
               + (size_t)tb * T_PER_BLOCK) * F4 + tid;

    const int t0 = tb * T_PER_BLOCK;

    #pragma unroll
    for (int k = 0; k < T_PER_BLOCK; k++) {
        int ts = t0 + k + s;
        if (ts >= T_DIM) ts -= T_DIM;     // s < 1024, t < 1024 -> one subtract
        orow[k * F4] = __ldg(&xrow[(size_t)ts * F4 + tid]);
    }
}

// ---------------------------------------------------------------------------
// Launch
// ---------------------------------------------------------------------------
extern "C" void kernel_launch(void* const* d_in, const int* in_sizes, int n_in,
                              void* d_out, int out_size)
{
    const float* x  = (const float*)d_in[0];   // (4,2,1024,1024)
    const float* dm = (const float*)d_in[1];   // (4,16)
    const float* df = (const float*)d_in[2];   // (1024,)

    float* out = (float*)d_out;
    // Output layout: dedispersed (4,16,2,1024,1024) then delays (4,16,1024)
    float* delays = out + (size_t)B_DIM * D_DIM * P_DIM * T_DIM * F_DIM;

    dedisp_prep_kernel<<<B_DIM * D_DIM, 128>>>(dm, df, delays);

    const int nblocks = B_DIM * D_DIM * P_DIM * (T_DIM / T_PER_BLOCK); // 16384
    dedisp_gather_kernel<<<nblocks, 256>>>((const float4*)x, (float4*)out);
}